// round 16
// baseline (speedup 1.0000x reference)
#include <cuda_runtime.h>
#include <cuda_fp16.h>
#include <cstdint>

// ---------------------------------------------------------------------------
// Problem constants
// ---------------------------------------------------------------------------
#define TOKENS  4096
#define IN_DIM  4096
#define OUT_DIM 4096
#define RANKL   16
#define LSCALE  2.0f   // lora_alpha / r = 32/16
#define KPAD    64     // LoRA K-slab padded to one BK

// Static device scratch (allowed)
__device__ __half g_Xh[(size_t)TOKENS * IN_DIM];   // fp16 activations
__device__ __half g_Wh[(size_t)OUT_DIM * IN_DIM];  // fp16 dequantized weight
__device__ __half g_Ah[(size_t)RANKL * IN_DIM];    // fp16 lora_A
__device__ __half g_Xa[(size_t)TOKENS * KPAD];     // fp16 2*(x@A^T), padded to 64
__device__ __half g_Bh[(size_t)OUT_DIM * KPAD];    // fp16 B, padded to 64

__constant__ float c_nf4[16] = {
    -1.0f, -0.6961928009986877f, -0.5250730514526367f, -0.39491748809814453f,
    -0.28444138169288635f, -0.18477343022823334f, -0.09105003625154495f, 0.0f,
    0.07958029955625534f, 0.16093020141124725f, 0.24611230194568634f, 0.33791524171829224f,
    0.44070982933044434f, 0.5626170039176941f, 0.7229568362236023f, 1.0f};

// ---------------------------------------------------------------------------
// Helpers (base ISA only: cp.async / ldmatrix / mma.sync / mbarrier)
// ---------------------------------------------------------------------------
__device__ __forceinline__ uint32_t smem_u32(const void* p) {
    uint32_t a;
    asm("{ .reg .u64 t; cvta.to.shared.u64 t, %1; cvt.u32.u64 %0, t; }" : "=r"(a) : "l"(p));
    return a;
}

#define SWZ128(b) ((b) ^ (((b) >> 3) & 0x70))

__device__ __forceinline__ void cp16(uint32_t dst, const void* src) {
    asm volatile("cp.async.cg.shared.global [%0], [%1], 16;" :: "r"(dst), "l"(src));
}
#define CP_COMMIT() asm volatile("cp.async.commit_group;" ::: "memory")
#define CP_WAIT(n)  asm volatile("cp.async.wait_group %0;" :: "n"(n) : "memory")

#define MBAR_INIT(addr, cnt) \
    asm volatile("mbarrier.init.shared.b64 [%0], %1;" :: "r"(addr), "r"((uint32_t)(cnt)) : "memory")

#define CPASYNC_ARRIVE_NOINC(addr) \
    asm volatile("cp.async.mbarrier.arrive.noinc.shared.b64 [%0];" :: "r"(addr) : "memory")

#define MBAR_ARRIVE(addr) \
    asm volatile("mbarrier.arrive.shared.b64 _, [%0];" :: "r"(addr) : "memory")

#define MBAR_WAIT(addr, parity) do {                                            \
    uint32_t _m = (addr); uint32_t _p = (parity); uint32_t _d;                  \
    asm volatile("{\n .reg .pred p;\n"                                          \
        " mbarrier.try_wait.parity.acquire.cta.shared::cta.b64 p, [%1], %2;\n"  \
        " selp.b32 %0, 1, 0, p;\n}"                                             \
        : "=r"(_d) : "r"(_m), "r"(_p) : "memory");                              \
    if (!_d) {                                                                  \
        asm volatile("{\n .reg .pred P1;\n"                                     \
            "W_%=:\n"                                                           \
            " mbarrier.try_wait.parity.acquire.cta.shared::cta.b64 P1, [%0], %1, 0x989680;\n" \
            " @P1 bra.uni D_%=;\n bra.uni W_%=;\nD_%=:\n}"                      \
            :: "r"(_m), "r"(_p) : "memory");                                    \
    }                                                                           \
} while (0)

__device__ __forceinline__ void ldm_x4(uint32_t& r0, uint32_t& r1, uint32_t& r2, uint32_t& r3,
                                       uint32_t addr) {
    asm volatile("ldmatrix.sync.aligned.m8n8.x4.shared.b16 {%0,%1,%2,%3}, [%4];"
                 : "=r"(r0), "=r"(r1), "=r"(r2), "=r"(r3) : "r"(addr));
}

__device__ __forceinline__ void mma16816(float& d0, float& d1, float& d2, float& d3,
                                         uint32_t a0, uint32_t a1, uint32_t a2, uint32_t a3,
                                         uint32_t b0, uint32_t b1) {
    asm volatile(
        "mma.sync.aligned.m16n8k16.row.col.f32.f16.f16.f32 "
        "{%0,%1,%2,%3}, {%4,%5,%6,%7}, {%8,%9}, {%0,%1,%2,%3};"
        : "+f"(d0), "+f"(d1), "+f"(d2), "+f"(d3)
        : "r"(a0), "r"(a1), "r"(a2), "r"(a3), "r"(b0), "r"(b1));
}

// ---------------------------------------------------------------------------
// Prep kernel 1 (ALL streaming, no dynamic smem, ONE launch) — R14 form.
// ---------------------------------------------------------------------------
#define CV_BLOCKS 2048
#define DQ_BLOCKS 2048
#define PB_BLOCKS 16
#define ACV_BLOCKS 16
#define PREP_GRID (CV_BLOCKS + DQ_BLOCKS + PB_BLOCKS + ACV_BLOCKS)

__global__ void __launch_bounds__(256) k_prep(
    const float* __restrict__ x, const float* __restrict__ A,
    const int* __restrict__ codes, const float* __restrict__ scales,
    const float* __restrict__ Bm) {
    int tid = threadIdx.x;
    int bx = blockIdx.x;

    if (bx < CV_BLOCKS) {
        size_t base4 = (size_t)bx * 2048;
        const float4* xb = reinterpret_cast<const float4*>(x);
#pragma unroll
        for (int itr = 0; itr < 8; itr++) {
            size_t f4 = base4 + itr * 256 + tid;
            float4 v = xb[f4];
            __half2 h01 = __floats2half2_rn(v.x, v.y);
            __half2 h23 = __floats2half2_rn(v.z, v.w);
            uint2 u;
            u.x = *reinterpret_cast<uint32_t*>(&h01);
            u.y = *reinterpret_cast<uint32_t*>(&h23);
            reinterpret_cast<uint2*>(g_Xh)[f4] = u;
        }
    } else if (bx < CV_BLOCKS + DQ_BLOCKS) {
        __shared__ float lut[16];
        if (tid < 16) lut[tid] = c_nf4[tid];
        __syncthreads();

        size_t base4 = (size_t)(bx - CV_BLOCKS) * 2048;
        const int4* cbase = reinterpret_cast<const int4*>(codes);
#pragma unroll
        for (int itr = 0; itr < 8; itr++) {
            size_t i4 = base4 + itr * 256 + tid;
            int4 c = cbase[i4];
            float sc = scales[i4 >> 4];
            __half2 h0 = __floats2half2_rn(lut[c.x] * sc, lut[c.y] * sc);
            __half2 h1 = __floats2half2_rn(lut[c.z] * sc, lut[c.w] * sc);
            uint2 u;
            u.x = *reinterpret_cast<uint32_t*>(&h0);
            u.y = *reinterpret_cast<uint32_t*>(&h1);
            *reinterpret_cast<uint2*>(g_Wh + i4 * 4) = u;
        }
    } else if (bx < CV_BLOCKS + DQ_BLOCKS + PB_BLOCKS) {
        int n = (bx - CV_BLOCKS - DQ_BLOCKS) * 256 + tid;
        const float4* src = reinterpret_cast<const float4*>(Bm + (size_t)n * RANKL);
        __half* dst = g_Bh + (size_t)n * KPAD;
        uint2 u[4];
#pragma unroll
        for (int q = 0; q < 4; q++) {
            float4 v = src[q];
            __half2 h01 = __floats2half2_rn(v.x, v.y);
            __half2 h23 = __floats2half2_rn(v.z, v.w);
            u[q].x = *reinterpret_cast<uint32_t*>(&h01);
            u[q].y = *reinterpret_cast<uint32_t*>(&h23);
        }
#pragma unroll
        for (int q = 0; q < 4; q++) *reinterpret_cast<uint2*>(dst + q * 4) = u[q];
        uint4 z = make_uint4(0, 0, 0, 0);
#pragma unroll
        for (int c = 16; c < KPAD; c += 8) *reinterpret_cast<uint4*>(dst + c) = z;
    } else {
        size_t base4 = (size_t)(bx - CV_BLOCKS - DQ_BLOCKS - PB_BLOCKS) * 1024;
        const float4* ab = reinterpret_cast<const float4*>(A);
#pragma unroll
        for (int itr = 0; itr < 4; itr++) {
            size_t f4 = base4 + itr * 256 + tid;
            float4 v = ab[f4];
            __half2 h01 = __floats2half2_rn(v.x, v.y);
            __half2 h23 = __floats2half2_rn(v.z, v.w);
            uint2 u;
            u.x = *reinterpret_cast<uint32_t*>(&h01);
            u.y = *reinterpret_cast<uint32_t*>(&h23);
            reinterpret_cast<uint2*>(g_Ah)[f4] = u;
        }
    }
}

// ---------------------------------------------------------------------------
// Prep kernel 2: Xa = fp16( LSCALE * Xh @ Ah^T ) — R14 form (tensor cores).
// ---------------------------------------------------------------------------
#define XA_CTAS   (TOKENS / 16)    // 256
#define XA_THREADS 128
struct XaSmem {
    __align__(1024) char tiles[4 * 2 * 4096];
    float red[4 * 16 * 16];
};

__global__ void __launch_bounds__(XA_THREADS) k_xa(int dummy) {
    __shared__ XaSmem sm;
    uint32_t sbase = smem_u32(sm.tiles);

    int tid = threadIdx.x;
    int lane = tid & 31;
    int wid = tid >> 5;
    int rows0 = blockIdx.x * 16;

    uint32_t wbase = sbase + wid * 8192;

    auto load_chunk = [&](int cglob, int stage) {
        uint32_t sX = wbase + stage * 4096;
        uint32_t sAh = sX + 2048;
        int koff = cglob * 64;
#pragma unroll
        for (int i = 0; i < 4; i++) {
            int idx = lane + i * 32;
            int r = idx >> 3, c8 = idx & 7;
            uint32_t sw = SWZ128(r * 128 + c8 * 16);
            cp16(sX + sw, g_Xh + (size_t)(rows0 + r) * IN_DIM + koff + c8 * 8);
            cp16(sAh + sw, g_Ah + (size_t)r * IN_DIM + koff + c8 * 8);
        }
    };

    int mi = lane >> 3;
    int r8 = lane & 7;
    int rowhalf = (mi & 1) * 8 + r8;
    uint32_t khalf = (uint32_t)((mi >> 1) * 16);
    uint32_t fragoff = (uint32_t)rowhalf * 128 + (khalf ^ (uint32_t)((rowhalf & 7) << 4));

    float acc[2][4];
#pragma unroll
    for (int i = 0; i < 2; i++)
#pragma unroll
        for (int k = 0; k < 4; k++) acc[i][k] = 0.f;

    int c0 = wid * 16;
    load_chunk(c0, 0);
    CP_COMMIT();

    for (int c = 0; c < 16; c++) {
        if (c + 1 < 16) load_chunk(c0 + c + 1, (c + 1) & 1);
        CP_COMMIT();
        CP_WAIT(1);
        __syncwarp();

        uint32_t sX = wbase + (c & 1) * 4096;
#pragma unroll
        for (int kk = 0; kk < 4; kk++) {
            uint32_t kx = (uint32_t)(kk * 32);
            uint32_t a0, a1, a2, a3, b0, b1, b2, b3;
            ldm_x4(a0, a1, a2, a3, sX + (fragoff ^ kx));
            ldm_x4(b0, b1, b2, b3, sX + 2048 + (fragoff ^ kx));
            mma16816(acc[0][0], acc[0][1], acc[0][2], acc[0][3], a0, a1, a2, a3, b0, b2);
            mma16816(acc[1][0], acc[1][1], acc[1][2], acc[1][3], a0, a1, a2, a3, b1, b3);
        }
        __syncwarp();
    }

#pragma unroll
    for (int nw = 0; nw < 2; nw++)
#pragma unroll
        for (int i = 0; i < 4; i++) {
            int row = (lane >> 2) + (i >> 1) * 8;
            int col = nw * 8 + (lane & 3) * 2 + (i & 1);
            sm.red[wid * 256 + row * 16 + col] = acc[nw][i];
        }
    __syncthreads();

    if (wid == 0) {
        int row = lane >> 1;
        int cb = (lane & 1) * 8;
        float v[8];
#pragma unroll
        for (int j = 0; j < 8; j++) {
            int col = cb + j;
            float s = sm.red[row * 16 + col] + sm.red[256 + row * 16 + col] +
                      sm.red[512 + row * 16 + col] + sm.red[768 + row * 16 + col];
            v[j] = LSCALE * s;
        }
        uint4 o;
        __half2 p0 = __floats2half2_rn(v[0], v[1]);
        __half2 p1 = __floats2half2_rn(v[2], v[3]);
        __half2 p2 = __floats2half2_rn(v[4], v[5]);
        __half2 p3 = __floats2half2_rn(v[6], v[7]);
        o.x = *reinterpret_cast<uint32_t*>(&p0);
        o.y = *reinterpret_cast<uint32_t*>(&p1);
        o.z = *reinterpret_cast<uint32_t*>(&p2);
        o.w = *reinterpret_cast<uint32_t*>(&p3);
        *reinterpret_cast<uint4*>(g_Xa + (size_t)(rows0 + row) * KPAD + cb) = o;
    }
    if (tid < 96) {
        int r = tid / 6, s = tid % 6;
        uint4 z = make_uint4(0, 0, 0, 0);
        *reinterpret_cast<uint4*>(g_Xa + (size_t)(rows0 + r) * KPAD + 16 + s * 8) = z;
    }
    (void)dummy;
}

// ---------------------------------------------------------------------------
// GEMM common config. 32 m-tiles x 32 n-tiles = 1024 tiles.
// Main covers linear tile ids [0, 888) = exactly 3 waves of 296 (148 SMs x 2);
// tail covers ids [888, 1024) = 136 tiles, each split in N into two 128x64
// jobs -> 272 CTAs = one short partial wave.
// ---------------------------------------------------------------------------
#define BM 128
#define BN 128
#define BK 64
#define NST 3
#define A_BYTES     (BM * BK * 2)               // 16384
#define B_BYTES     (BN * BK * 2)               // 16384
#define STAGE_BYTES (A_BYTES + B_BYTES)         // 32768
#define GEMM_SMEM   (1024 + NST * STAGE_BYTES)  // 99328
#define KMAIN       (IN_DIM / BK)               // 64
#define KTOT        (KMAIN + 1)                 // 65

#define MAIN_TILES 888                          // 296 * 3 exact waves
#define TAIL_TILES (1024 - MAIN_TILES)          // 136

// ---------------------------------------------------------------------------
// Main GEMM (R9/R13-exact pipeline, frozen; 1-D grid of linear tile ids).
// ---------------------------------------------------------------------------
__global__ void __launch_bounds__(256, 2) k_gemm(float* __restrict__ out) {
    extern __shared__ char dsm[];
    uint32_t hdr = smem_u32(dsm);
    uint32_t tiles = hdr + 1024;

    int tid = threadIdx.x;
    int lane = tid & 31;
    int wid = tid >> 5;
    int wm = wid >> 1;
    int wn = wid & 1;
    int tileid = blockIdx.x;                 // 0..887
    int m0 = (tileid >> 5) * BM;             // m-tile 0..27
    int n0 = (tileid & 31) * BN;             // n-tile 0..31

    if (tid == 0) {
#pragma unroll
        for (int s = 0; s < NST; s++) {
            MBAR_INIT(hdr + s * 8, 256);
            MBAR_INIT(hdr + 24 + s * 8, 256);
        }
    }
    __syncthreads();

    int lr = tid >> 3, lc = tid & 7;
    uint32_t s0 = SWZ128(lr * 128 + lc * 16);
    int gmain = lr * IN_DIM + lc * 8;
    int gside = lr * KPAD + lc * 8;

    const __half* gXm = g_Xh + (size_t)m0 * IN_DIM;
    const __half* gWn = g_Wh + (size_t)n0 * IN_DIM;
    const __half* gXa = g_Xa + (size_t)m0 * KPAD;
    const __half* gBh = g_Bh + (size_t)n0 * KPAD;

    auto do_load = [&](int kq, int stage) {
        uint32_t sA = tiles + stage * STAGE_BYTES;
        uint32_t sB = sA + A_BYTES;
        if (kq < KMAIN) {
            const __half* ga = gXm + kq * BK;
            const __half* gb = gWn + kq * BK;
#pragma unroll
            for (int i = 0; i < 4; i++)
                cp16(sA + s0 + i * (32 * 128), ga + gmain + i * (32 * IN_DIM));
#pragma unroll
            for (int i = 0; i < 4; i++)
                cp16(sB + s0 + i * (32 * 128), gb + gmain + i * (32 * IN_DIM));
        } else {
#pragma unroll
            for (int i = 0; i < 4; i++)
                cp16(sA + s0 + i * (32 * 128), gXa + gside + i * (32 * KPAD));
#pragma unroll
            for (int i = 0; i < 4; i++)
                cp16(sB + s0 + i * (32 * 128), gBh + gside + i * (32 * KPAD));
        }
    };

    float acc[2][8][4];
#pragma unroll
    for (int i = 0; i < 2; i++)
#pragma unroll
        for (int j = 0; j < 8; j++)
#pragma unroll
            for (int k = 0; k < 4; k++) acc[i][j][k] = 0.f;

    do_load(0, 0); CPASYNC_ARRIVE_NOINC(hdr + 0);
    do_load(1, 1); CPASYNC_ARRIVE_NOINC(hdr + 8);
    do_load(2, 2); CPASYNC_ARRIVE_NOINC(hdr + 16);

    int mi = lane >> 3;
    int r8 = lane & 7;
    int rowhalf = (mi & 1) * 8 + r8;
    uint32_t khalf = (uint32_t)((mi >> 1) * 16);

    uint32_t abase[2], bbase[4];
#pragma unroll
    for (int mt = 0; mt < 2; mt++) {
        int row = wm * 32 + mt * 16 + rowhalf;
        abase[mt] = (uint32_t)row * 128 + (khalf ^ (uint32_t)((row & 7) << 4));
    }
#pragma unroll
    for (int nb = 0; nb < 4; nb++) {
        int row = wn * 64 + nb * 16 + rowhalf;
        bbase[nb] = A_BYTES + (uint32_t)row * 128 + (khalf ^ (uint32_t)((row & 7) << 4));
    }

    for (int it = 0; it < KTOT; it++) {
        int b = it % NST;
        MBAR_WAIT(hdr + b * 8, (it / NST) & 1);
        uint32_t sS = tiles + b * STAGE_BYTES;

#pragma unroll
        for (int kk = 0; kk < 4; kk++) {
            uint32_t kx = (uint32_t)(kk * 32);
            uint32_t a[2][4];
#pragma unroll
            for (int mt = 0; mt < 2; mt++)
                ldm_x4(a[mt][0], a[mt][1], a[mt][2], a[mt][3],
                       sS + (abase[mt] ^ kx));
            uint32_t b4[4][4];
#pragma unroll
            for (int nb = 0; nb < 4; nb++)
                ldm_x4(b4[nb][0], b4[nb][1], b4[nb][2], b4[nb][3],
                       sS + (bbase[nb] ^ kx));
#pragma unroll
            for (int mt = 0; mt < 2; mt++)
#pragma unroll
                for (int nb = 0; nb < 4; nb++)
#pragma unroll
                    for (int w = 0; w < 2; w++)
                        mma16816(acc[mt][nb * 2 + w][0], acc[mt][nb * 2 + w][1],
                                 acc[mt][nb * 2 + w][2], acc[mt][nb * 2 + w][3],
                                 a[mt][0], a[mt][1], a[mt][2], a[mt][3],
                                 b4[nb][w], b4[nb][w + 2]);
        }

        MBAR_ARRIVE(hdr + 24 + b * 8);

        int s3 = it + NST;
        if (s3 < KTOT) {
            MBAR_WAIT(hdr + 24 + b * 8, (it / NST) & 1);
            do_load(s3, b);
            CPASYNC_ARRIVE_NOINC(hdr + b * 8);
        }
    }

#pragma unroll
    for (int mt = 0; mt < 2; mt++) {
#pragma unroll
        for (int nb = 0; nb < 4; nb++)
#pragma unroll
            for (int w = 0; w < 2; w++) {
                int nt = nb * 2 + w;
                int row0 = m0 + wm * 32 + mt * 16 + (lane >> 2);
                int col = n0 + wn * 64 + nb * 16 + w * 8 + (lane & 3) * 2;
                float2 v0 = make_float2(acc[mt][nt][0], acc[mt][nt][1]);
                float2 v1 = make_float2(acc[mt][nt][2], acc[mt][nt][3]);
                *reinterpret_cast<float2*>(out + (size_t)row0 * OUT_DIM + col) = v0;
                *reinterpret_cast<float2*>(out + (size_t)(row0 + 8) * OUT_DIM + col) = v1;
            }
    }
}

// ---------------------------------------------------------------------------
// Tail GEMM: tile ids 888..1023 (136 tiles), each split in N into two
// 128x64 jobs -> 272 CTAs. 8 warps 4Mx2N, warp tile 32x32 (R12-verified
// layout). Full K per output element -> identical accumulation order.
// ---------------------------------------------------------------------------
#define TBN 64
#define TB_BYTES (TBN * BK * 2)                  // 8192
#define TSTAGE   (A_BYTES + TB_BYTES)            // 24576
#define TAIL_SMEM (1024 + NST * TSTAGE)          // 74752

__global__ void __launch_bounds__(256, 2) k_gemm_tail(float* __restrict__ out) {
    extern __shared__ char dsm[];
    uint32_t hdr = smem_u32(dsm);
    uint32_t tiles = hdr + 1024;

    int tid = threadIdx.x;
    int lane = tid & 31;
    int wid = tid >> 5;
    int wm = wid >> 1;    // 0..3 (M, 32 rows each)
    int wn = wid & 1;     // 0..1 (N, 32 cols each)

    int j = blockIdx.x;                  // 0..271
    int t = MAIN_TILES + (j >> 1);       // tile id 888..1023
    int m0 = (t >> 5) * BM;              // m-tile 27..31
    int n0 = (t & 31) * BN + (j & 1) * TBN;

    if (tid == 0) {
#pragma unroll
        for (int s = 0; s < NST; s++) {
            MBAR_INIT(hdr + s * 8, 256);
            MBAR_INIT(hdr + 24 + s * 8, 256);
        }
    }
    __syncthreads();

    int lr = tid >> 3, lc = tid & 7;
    uint32_t s0 = SWZ128(lr * 128 + lc * 16);
    int gmain = lr * IN_DIM + lc * 8;
    int gside = lr * KPAD + lc * 8;

    const __half* gXm = g_Xh + (size_t)m0 * IN_DIM;
    const __half* gWn = g_Wh + (size_t)n0 * IN_DIM;
    const __half* gXa = g_Xa + (size_t)m0 * KPAD;
    const __half* gBh = g_Bh + (size_t)n0 * KPAD;

    auto do_load = [&](int kq, int stage) {
        uint32_t sA = tiles + stage * TSTAGE;
        uint32_t sB = sA + A_BYTES;
        if (kq < KMAIN) {
            const __half* ga = gXm + kq * BK;
            const __half* gb = gWn + kq * BK;
#pragma unroll
            for (int i = 0; i < 4; i++)      // A: 128 rows
                cp16(sA + s0 + i * (32 * 128), ga + gmain + i * (32 * IN_DIM));
#pragma unroll
            for (int i = 0; i < 2; i++)      // B: 64 rows
                cp16(sB + s0 + i * (32 * 128), gb + gmain + i * (32 * IN_DIM));
        } else {
#pragma unroll
            for (int i = 0; i < 4; i++)
                cp16(sA + s0 + i * (32 * 128), gXa + gside + i * (32 * KPAD));
#pragma unroll
            for (int i = 0; i < 2; i++)
                cp16(sB + s0 + i * (32 * 128), gBh + gside + i * (32 * KPAD));
        }
    };

    float acc[2][4][4];
#pragma unroll
    for (int i = 0; i < 2; i++)
#pragma unroll
        for (int jx = 0; jx < 4; jx++)
#pragma unroll
            for (int k = 0; k < 4; k++) acc[i][jx][k] = 0.f;

    do_load(0, 0); CPASYNC_ARRIVE_NOINC(hdr + 0);
    do_load(1, 1); CPASYNC_ARRIVE_NOINC(hdr + 8);
    do_load(2, 2); CPASYNC_ARRIVE_NOINC(hdr + 16);

    int mi = lane >> 3;
    int r8 = lane & 7;
    int rowhalf = (mi & 1) * 8 + r8;
    uint32_t khalf = (uint32_t)((mi >> 1) * 16);

    uint32_t abase[2], bbase[2];
#pragma unroll
    for (int mt = 0; mt < 2; mt++) {
        int row = wm * 32 + mt * 16 + rowhalf;
        abase[mt] = (uint32_t)row * 128 + (khalf ^ (uint32_t)((row & 7) << 4));
    }
#pragma unroll
    for (int nb = 0; nb < 2; nb++) {
        int row = wn * 32 + nb * 16 + rowhalf;
        bbase[nb] = A_BYTES + (uint32_t)row * 128 + (khalf ^ (uint32_t)((row & 7) << 4));
    }

    for (int it = 0; it < KTOT; it++) {
        int b = it % NST;
        MBAR_WAIT(hdr + b * 8, (it / NST) & 1);
        uint32_t sS = tiles + b * TSTAGE;

#pragma unroll
        for (int kk = 0; kk < 4; kk++) {
            uint32_t kx = (uint32_t)(kk * 32);
            uint32_t a[2][4];
#pragma unroll
            for (int mt = 0; mt < 2; mt++)
                ldm_x4(a[mt][0], a[mt][1], a[mt][2], a[mt][3],
                       sS + (abase[mt] ^ kx));
            uint32_t b4[2][4];
#pragma unroll
            for (int nb = 0; nb < 2; nb++)
                ldm_x4(b4[nb][0], b4[nb][1], b4[nb][2], b4[nb][3],
                       sS + (bbase[nb] ^ kx));
#pragma unroll
            for (int mt = 0; mt < 2; mt++)
#pragma unroll
                for (int nb = 0; nb < 2; nb++)
#pragma unroll
                    for (int w = 0; w < 2; w++)
                        mma16816(acc[mt][nb * 2 + w][0], acc[mt][nb * 2 + w][1],
                                 acc[mt][nb * 2 + w][2], acc[mt][nb * 2 + w][3],
                                 a[mt][0], a[mt][1], a[mt][2], a[mt][3],
                                 b4[nb][w], b4[nb][w + 2]);
        }

        MBAR_ARRIVE(hdr + 24 + b * 8);

        int s3 = it + NST;
        if (s3 < KTOT) {
            MBAR_WAIT(hdr + 24 + b * 8, (it / NST) & 1);
            do_load(s3, b);
            CPASYNC_ARRIVE_NOINC(hdr + b * 8);
        }
    }

#pragma unroll
    for (int mt = 0; mt < 2; mt++) {
#pragma unroll
        for (int nb = 0; nb < 2; nb++)
#pragma unroll
            for (int w = 0; w < 2; w++) {
                int nt = nb * 2 + w;
                int row0 = m0 + wm * 32 + mt * 16 + (lane >> 2);
                int col = n0 + wn * 32 + nb * 16 + w * 8 + (lane & 3) * 2;
                float2 v0 = make_float2(acc[mt][nt][0], acc[mt][nt][1]);
                float2 v1 = make_float2(acc[mt][nt][2], acc[mt][nt][3]);
                *reinterpret_cast<float2*>(out + (size_t)row0 * OUT_DIM + col) = v0;
                *reinterpret_cast<float2*>(out + (size_t)(row0 + 8) * OUT_DIM + col) = v1;
            }
    }
}

// ---------------------------------------------------------------------------
// Launch
// ---------------------------------------------------------------------------
extern "C" void kernel_launch(void* const* d_in, const int* in_sizes, int n_in,
                              void* d_out, int out_size) {
    const float* x      = (const float*)d_in[0];
    const int*   codes  = (const int*)d_in[1];
    const float* scales = (const float*)d_in[2];
    const float* lora_A = (const float*)d_in[3];
    const float* lora_B = (const float*)d_in[4];
    float* out = (float*)d_out;

    (void)in_sizes; (void)n_in; (void)out_size;

    // 1) streaming prep: x->fp16, dequant, B, A->fp16
    k_prep<<<PREP_GRID, 256>>>(x, lora_A, codes, scales, lora_B);

    // 2) Xa = 2*(Xh @ Ah^T) on tensor cores
    k_xa<<<XA_CTAS, XA_THREADS>>>(0);

    // 3) GEMM main: tile ids [0, 888) = exactly 3 full waves (148 SMs x 2)
    cudaFuncSetAttribute(k_gemm, cudaFuncAttributeMaxDynamicSharedMemorySize, GEMM_SMEM);
    k_gemm<<<MAIN_TILES, 256, GEMM_SMEM>>>(out);

    // 4) GEMM tail: ids [888, 1024) split in N -> 272 half-width CTAs
    cudaFuncSetAttribute(k_gemm_tail, cudaFuncAttributeMaxDynamicSharedMemorySize, TAIL_SMEM);
    k_gemm_tail<<<2 * TAIL_TILES, 256, TAIL_SMEM>>>(out);
}

// round 17
// speedup vs baseline: 1.0388x; 1.0388x over previous
#include <cuda_runtime.h>
#include <cuda_fp16.h>
#include <cstdint>

// ---------------------------------------------------------------------------
// Problem constants
// ---------------------------------------------------------------------------
#define TOKENS  4096
#define IN_DIM  4096
#define OUT_DIM 4096
#define RANKL   16
#define LSCALE  2.0f   // lora_alpha / r = 32/16
#define KPAD    64     // LoRA K-slab padded to one BK

// Static device scratch (allowed)
__device__ __half g_Xh[(size_t)TOKENS * IN_DIM];   // fp16 activations
__device__ __half g_Wh[(size_t)OUT_DIM * IN_DIM];  // fp16 dequantized weight
__device__ __half g_Ah[(size_t)RANKL * IN_DIM];    // fp16 lora_A
__device__ __half g_Xa[(size_t)TOKENS * KPAD];     // fp16 2*(x@A^T), padded to 64
__device__ __half g_Bh[(size_t)OUT_DIM * KPAD];    // fp16 B, padded to 64

__constant__ float c_nf4[16] = {
    -1.0f, -0.6961928009986877f, -0.5250730514526367f, -0.39491748809814453f,
    -0.28444138169288635f, -0.18477343022823334f, -0.09105003625154495f, 0.0f,
    0.07958029955625534f, 0.16093020141124725f, 0.24611230194568634f, 0.33791524171829224f,
    0.44070982933044434f, 0.5626170039176941f, 0.7229568362236023f, 1.0f};

// ---------------------------------------------------------------------------
// Helpers (base ISA only: cp.async / ldmatrix / mma.sync / mbarrier)
// ---------------------------------------------------------------------------
__device__ __forceinline__ uint32_t smem_u32(const void* p) {
    uint32_t a;
    asm("{ .reg .u64 t; cvta.to.shared.u64 t, %1; cvt.u32.u64 %0, t; }" : "=r"(a) : "l"(p));
    return a;
}

#define SWZ128(b) ((b) ^ (((b) >> 3) & 0x70))

__device__ __forceinline__ void cp16(uint32_t dst, const void* src) {
    asm volatile("cp.async.cg.shared.global [%0], [%1], 16;" :: "r"(dst), "l"(src));
}
#define CP_COMMIT() asm volatile("cp.async.commit_group;" ::: "memory")
#define CP_WAIT(n)  asm volatile("cp.async.wait_group %0;" :: "n"(n) : "memory")

#define MBAR_INIT(addr, cnt) \
    asm volatile("mbarrier.init.shared.b64 [%0], %1;" :: "r"(addr), "r"((uint32_t)(cnt)) : "memory")

#define CPASYNC_ARRIVE_NOINC(addr) \
    asm volatile("cp.async.mbarrier.arrive.noinc.shared.b64 [%0];" :: "r"(addr) : "memory")

#define MBAR_ARRIVE(addr) \
    asm volatile("mbarrier.arrive.shared.b64 _, [%0];" :: "r"(addr) : "memory")

#define MBAR_WAIT(addr, parity) do {                                            \
    uint32_t _m = (addr); uint32_t _p = (parity); uint32_t _d;                  \
    asm volatile("{\n .reg .pred p;\n"                                          \
        " mbarrier.try_wait.parity.acquire.cta.shared::cta.b64 p, [%1], %2;\n"  \
        " selp.b32 %0, 1, 0, p;\n}"                                             \
        : "=r"(_d) : "r"(_m), "r"(_p) : "memory");                              \
    if (!_d) {                                                                  \
        asm volatile("{\n .reg .pred P1;\n"                                     \
            "W_%=:\n"                                                           \
            " mbarrier.try_wait.parity.acquire.cta.shared::cta.b64 P1, [%0], %1, 0x989680;\n" \
            " @P1 bra.uni D_%=;\n bra.uni W_%=;\nD_%=:\n}"                      \
            :: "r"(_m), "r"(_p) : "memory");                                    \
    }                                                                           \
} while (0)

__device__ __forceinline__ void ldm_x4(uint32_t& r0, uint32_t& r1, uint32_t& r2, uint32_t& r3,
                                       uint32_t addr) {
    asm volatile("ldmatrix.sync.aligned.m8n8.x4.shared.b16 {%0,%1,%2,%3}, [%4];"
                 : "=r"(r0), "=r"(r1), "=r"(r2), "=r"(r3) : "r"(addr));
}

__device__ __forceinline__ void mma16816(float& d0, float& d1, float& d2, float& d3,
                                         uint32_t a0, uint32_t a1, uint32_t a2, uint32_t a3,
                                         uint32_t b0, uint32_t b1) {
    asm volatile(
        "mma.sync.aligned.m16n8k16.row.col.f32.f16.f16.f32 "
        "{%0,%1,%2,%3}, {%4,%5,%6,%7}, {%8,%9}, {%0,%1,%2,%3};"
        : "+f"(d0), "+f"(d1), "+f"(d2), "+f"(d3)
        : "r"(a0), "r"(a1), "r"(a2), "r"(a3), "r"(b0), "r"(b1));
}

// ---------------------------------------------------------------------------
// Prep kernel 1 (ALL streaming, no dynamic smem, ONE launch) — R14 form.
// ---------------------------------------------------------------------------
#define CV_BLOCKS 2048
#define DQ_BLOCKS 2048
#define PB_BLOCKS 16
#define ACV_BLOCKS 16
#define PREP_GRID (CV_BLOCKS + DQ_BLOCKS + PB_BLOCKS + ACV_BLOCKS)

__global__ void __launch_bounds__(256) k_prep(
    const float* __restrict__ x, const float* __restrict__ A,
    const int* __restrict__ codes, const float* __restrict__ scales,
    const float* __restrict__ Bm) {
    int tid = threadIdx.x;
    int bx = blockIdx.x;

    if (bx < CV_BLOCKS) {
        size_t base4 = (size_t)bx * 2048;
        const float4* xb = reinterpret_cast<const float4*>(x);
#pragma unroll
        for (int itr = 0; itr < 8; itr++) {
            size_t f4 = base4 + itr * 256 + tid;
            float4 v = xb[f4];
            __half2 h01 = __floats2half2_rn(v.x, v.y);
            __half2 h23 = __floats2half2_rn(v.z, v.w);
            uint2 u;
            u.x = *reinterpret_cast<uint32_t*>(&h01);
            u.y = *reinterpret_cast<uint32_t*>(&h23);
            reinterpret_cast<uint2*>(g_Xh)[f4] = u;
        }
    } else if (bx < CV_BLOCKS + DQ_BLOCKS) {
        __shared__ float lut[16];
        if (tid < 16) lut[tid] = c_nf4[tid];
        __syncthreads();

        size_t base4 = (size_t)(bx - CV_BLOCKS) * 2048;
        const int4* cbase = reinterpret_cast<const int4*>(codes);
#pragma unroll
        for (int itr = 0; itr < 8; itr++) {
            size_t i4 = base4 + itr * 256 + tid;
            int4 c = cbase[i4];
            float sc = scales[i4 >> 4];
            __half2 h0 = __floats2half2_rn(lut[c.x] * sc, lut[c.y] * sc);
            __half2 h1 = __floats2half2_rn(lut[c.z] * sc, lut[c.w] * sc);
            uint2 u;
            u.x = *reinterpret_cast<uint32_t*>(&h0);
            u.y = *reinterpret_cast<uint32_t*>(&h1);
            *reinterpret_cast<uint2*>(g_Wh + i4 * 4) = u;
        }
    } else if (bx < CV_BLOCKS + DQ_BLOCKS + PB_BLOCKS) {
        int n = (bx - CV_BLOCKS - DQ_BLOCKS) * 256 + tid;
        const float4* src = reinterpret_cast<const float4*>(Bm + (size_t)n * RANKL);
        __half* dst = g_Bh + (size_t)n * KPAD;
        uint2 u[4];
#pragma unroll
        for (int q = 0; q < 4; q++) {
            float4 v = src[q];
            __half2 h01 = __floats2half2_rn(v.x, v.y);
            __half2 h23 = __floats2half2_rn(v.z, v.w);
            u[q].x = *reinterpret_cast<uint32_t*>(&h01);
            u[q].y = *reinterpret_cast<uint32_t*>(&h23);
        }
#pragma unroll
        for (int q = 0; q < 4; q++) *reinterpret_cast<uint2*>(dst + q * 4) = u[q];
        uint4 z = make_uint4(0, 0, 0, 0);
#pragma unroll
        for (int c = 16; c < KPAD; c += 8) *reinterpret_cast<uint4*>(dst + c) = z;
    } else {
        size_t base4 = (size_t)(bx - CV_BLOCKS - DQ_BLOCKS - PB_BLOCKS) * 1024;
        const float4* ab = reinterpret_cast<const float4*>(A);
#pragma unroll
        for (int itr = 0; itr < 4; itr++) {
            size_t f4 = base4 + itr * 256 + tid;
            float4 v = ab[f4];
            __half2 h01 = __floats2half2_rn(v.x, v.y);
            __half2 h23 = __floats2half2_rn(v.z, v.w);
            uint2 u;
            u.x = *reinterpret_cast<uint32_t*>(&h01);
            u.y = *reinterpret_cast<uint32_t*>(&h23);
            reinterpret_cast<uint2*>(g_Ah)[f4] = u;
        }
    }
}

// ---------------------------------------------------------------------------
// Prep kernel 2: Xa = fp16( LSCALE * Xh @ Ah^T ), tensor cores.
// 256 CTAs x 16 rows; 8 warps split K (8 x BK=64 chunks each — serial chain
// HALVED vs R14) with warp-private double-buffered cp.async stages; fp32 smem
// reduction across 8 warps. Dynamic smem 72KB.
// ---------------------------------------------------------------------------
#define XA_CTAS   (TOKENS / 16)    // 256
#define XA_THREADS 256
#define XA_TILES_BYTES (8 * 2 * 4096)             // 65536
#define XA_RED_BYTES   (8 * 256 * 4)              // 8192
#define XA_SMEM (XA_TILES_BYTES + XA_RED_BYTES)   // 73728

__global__ void __launch_bounds__(XA_THREADS) k_xa(int dummy) {
    extern __shared__ char xsm[];
    uint32_t sbase = smem_u32(xsm);
    float* red = reinterpret_cast<float*>(xsm + XA_TILES_BYTES);

    int tid = threadIdx.x;
    int lane = tid & 31;
    int wid = tid >> 5;                 // 0..7, warp = K-eighth owner
    int rows0 = blockIdx.x * 16;

    uint32_t wbase = sbase + wid * 8192;

    auto load_chunk = [&](int cglob, int stage) {
        uint32_t sX = wbase + stage * 4096;
        uint32_t sAh = sX + 2048;
        int koff = cglob * 64;
#pragma unroll
        for (int i = 0; i < 4; i++) {
            int idx = lane + i * 32;
            int r = idx >> 3, c8 = idx & 7;
            uint32_t sw = SWZ128(r * 128 + c8 * 16);
            cp16(sX + sw, g_Xh + (size_t)(rows0 + r) * IN_DIM + koff + c8 * 8);
            cp16(sAh + sw, g_Ah + (size_t)r * IN_DIM + koff + c8 * 8);
        }
    };

    int mi = lane >> 3;
    int r8 = lane & 7;
    int rowhalf = (mi & 1) * 8 + r8;
    uint32_t khalf = (uint32_t)((mi >> 1) * 16);
    uint32_t fragoff = (uint32_t)rowhalf * 128 + (khalf ^ (uint32_t)((rowhalf & 7) << 4));

    float acc[2][4];
#pragma unroll
    for (int i = 0; i < 2; i++)
#pragma unroll
        for (int k = 0; k < 4; k++) acc[i][k] = 0.f;

    int c0 = wid * 8;                   // this warp's K-chunks [c0, c0+8)
    load_chunk(c0, 0);
    CP_COMMIT();

    for (int c = 0; c < 8; c++) {
        if (c + 1 < 8) load_chunk(c0 + c + 1, (c + 1) & 1);
        CP_COMMIT();
        CP_WAIT(1);
        __syncwarp();

        uint32_t sX = wbase + (c & 1) * 4096;
#pragma unroll
        for (int kk = 0; kk < 4; kk++) {
            uint32_t kx = (uint32_t)(kk * 32);
            uint32_t a0, a1, a2, a3, b0, b1, b2, b3;
            ldm_x4(a0, a1, a2, a3, sX + (fragoff ^ kx));
            ldm_x4(b0, b1, b2, b3, sX + 2048 + (fragoff ^ kx));
            mma16816(acc[0][0], acc[0][1], acc[0][2], acc[0][3], a0, a1, a2, a3, b0, b2);
            mma16816(acc[1][0], acc[1][1], acc[1][2], acc[1][3], a0, a1, a2, a3, b1, b3);
        }
        __syncwarp();
    }

    // dump partials: red[wid][row][col]
#pragma unroll
    for (int nw = 0; nw < 2; nw++)
#pragma unroll
        for (int i = 0; i < 4; i++) {
            int row = (lane >> 2) + (i >> 1) * 8;
            int col = nw * 8 + (lane & 3) * 2 + (i & 1);
            red[wid * 256 + row * 16 + col] = acc[nw][i];
        }
    __syncthreads();

    // warp 0 reduces 8 partials, writes fp16 Xa (16 rows x 16 cols)
    if (wid == 0) {
        int row = lane >> 1;
        int cb = (lane & 1) * 8;
        float v[8];
#pragma unroll
        for (int j = 0; j < 8; j++) {
            int col = cb + j;
            float s = 0.f;
#pragma unroll
            for (int w = 0; w < 8; w++) s += red[w * 256 + row * 16 + col];
            v[j] = LSCALE * s;
        }
        uint4 o;
        __half2 p0 = __floats2half2_rn(v[0], v[1]);
        __half2 p1 = __floats2half2_rn(v[2], v[3]);
        __half2 p2 = __floats2half2_rn(v[4], v[5]);
        __half2 p3 = __floats2half2_rn(v[6], v[7]);
        o.x = *reinterpret_cast<uint32_t*>(&p0);
        o.y = *reinterpret_cast<uint32_t*>(&p1);
        o.z = *reinterpret_cast<uint32_t*>(&p2);
        o.w = *reinterpret_cast<uint32_t*>(&p3);
        *reinterpret_cast<uint4*>(g_Xa + (size_t)(rows0 + row) * KPAD + cb) = o;
    }
    // zero-pad cols 16..63 (96 uint4 across the CTA)
    if (tid < 96) {
        int r = tid / 6, s = tid % 6;
        uint4 z = make_uint4(0, 0, 0, 0);
        *reinterpret_cast<uint4*>(g_Xa + (size_t)(rows0 + r) * KPAD + 16 + s * 8) = z;
    }
    (void)dummy;
}

// ---------------------------------------------------------------------------
// GEMM  y[m,n] = sum_k [Xh|Xa][m,k] * [Wh|Bh][n,k]
// R9/R13/R14-exact frozen best: 128x128x64 block; 8 warps (4Mx2N), warp tile
// 32x64; 3-stage mbarrier pipeline, release AFTER MMA block; 2 CTAs/SM.
// Grid 32x32 tiles (wave-split disproven in R16).
// ---------------------------------------------------------------------------
#define BM 128
#define BN 128
#define BK 64
#define NST 3
#define A_BYTES     (BM * BK * 2)               // 16384
#define B_BYTES     (BN * BK * 2)               // 16384
#define STAGE_BYTES (A_BYTES + B_BYTES)         // 32768
#define GEMM_SMEM   (1024 + NST * STAGE_BYTES)  // 99328
#define KMAIN       (IN_DIM / BK)               // 64
#define KTOT        (KMAIN + 1)                 // 65

__global__ void __launch_bounds__(256, 2) k_gemm(float* __restrict__ out) {
    extern __shared__ char dsm[];
    uint32_t hdr = smem_u32(dsm);
    uint32_t tiles = hdr + 1024;

    int tid = threadIdx.x;
    int lane = tid & 31;
    int wid = tid >> 5;
    int wm = wid >> 1;
    int wn = wid & 1;
    int n0 = blockIdx.x * BN;
    int m0 = blockIdx.y * BM;

    if (tid == 0) {
#pragma unroll
        for (int s = 0; s < NST; s++) {
            MBAR_INIT(hdr + s * 8, 256);
            MBAR_INIT(hdr + 24 + s * 8, 256);
        }
    }
    __syncthreads();

    int lr = tid >> 3, lc = tid & 7;
    uint32_t s0 = SWZ128(lr * 128 + lc * 16);
    int gmain = lr * IN_DIM + lc * 8;
    int gside = lr * KPAD + lc * 8;

    const __half* gXm = g_Xh + (size_t)m0 * IN_DIM;
    const __half* gWn = g_Wh + (size_t)n0 * IN_DIM;
    const __half* gXa = g_Xa + (size_t)m0 * KPAD;
    const __half* gBh = g_Bh + (size_t)n0 * KPAD;

    auto do_load = [&](int kq, int stage) {
        uint32_t sA = tiles + stage * STAGE_BYTES;
        uint32_t sB = sA + A_BYTES;
        if (kq < KMAIN) {
            const __half* ga = gXm + kq * BK;
            const __half* gb = gWn + kq * BK;
#pragma unroll
            for (int i = 0; i < 4; i++)
                cp16(sA + s0 + i * (32 * 128), ga + gmain + i * (32 * IN_DIM));
#pragma unroll
            for (int i = 0; i < 4; i++)
                cp16(sB + s0 + i * (32 * 128), gb + gmain + i * (32 * IN_DIM));
        } else {
#pragma unroll
            for (int i = 0; i < 4; i++)
                cp16(sA + s0 + i * (32 * 128), gXa + gside + i * (32 * KPAD));
#pragma unroll
            for (int i = 0; i < 4; i++)
                cp16(sB + s0 + i * (32 * 128), gBh + gside + i * (32 * KPAD));
        }
    };

    float acc[2][8][4];
#pragma unroll
    for (int i = 0; i < 2; i++)
#pragma unroll
        for (int j = 0; j < 8; j++)
#pragma unroll
            for (int k = 0; k < 4; k++) acc[i][j][k] = 0.f;

    do_load(0, 0); CPASYNC_ARRIVE_NOINC(hdr + 0);
    do_load(1, 1); CPASYNC_ARRIVE_NOINC(hdr + 8);
    do_load(2, 2); CPASYNC_ARRIVE_NOINC(hdr + 16);

    int mi = lane >> 3;
    int r8 = lane & 7;
    int rowhalf = (mi & 1) * 8 + r8;
    uint32_t khalf = (uint32_t)((mi >> 1) * 16);

    uint32_t abase[2], bbase[4];
#pragma unroll
    for (int mt = 0; mt < 2; mt++) {
        int row = wm * 32 + mt * 16 + rowhalf;
        abase[mt] = (uint32_t)row * 128 + (khalf ^ (uint32_t)((row & 7) << 4));
    }
#pragma unroll
    for (int nb = 0; nb < 4; nb++) {
        int row = wn * 64 + nb * 16 + rowhalf;
        bbase[nb] = A_BYTES + (uint32_t)row * 128 + (khalf ^ (uint32_t)((row & 7) << 4));
    }

    for (int it = 0; it < KTOT; it++) {
        int b = it % NST;
        MBAR_WAIT(hdr + b * 8, (it / NST) & 1);
        uint32_t sS = tiles + b * STAGE_BYTES;

#pragma unroll
        for (int kk = 0; kk < 4; kk++) {
            uint32_t kx = (uint32_t)(kk * 32);
            uint32_t a[2][4];
#pragma unroll
            for (int mt = 0; mt < 2; mt++)
                ldm_x4(a[mt][0], a[mt][1], a[mt][2], a[mt][3],
                       sS + (abase[mt] ^ kx));
            uint32_t b4[4][4];
#pragma unroll
            for (int nb = 0; nb < 4; nb++)
                ldm_x4(b4[nb][0], b4[nb][1], b4[nb][2], b4[nb][3],
                       sS + (bbase[nb] ^ kx));
#pragma unroll
            for (int mt = 0; mt < 2; mt++)
#pragma unroll
                for (int nb = 0; nb < 4; nb++)
#pragma unroll
                    for (int w = 0; w < 2; w++)
                        mma16816(acc[mt][nb * 2 + w][0], acc[mt][nb * 2 + w][1],
                                 acc[mt][nb * 2 + w][2], acc[mt][nb * 2 + w][3],
                                 a[mt][0], a[mt][1], a[mt][2], a[mt][3],
                                 b4[nb][w], b4[nb][w + 2]);
        }

        MBAR_ARRIVE(hdr + 24 + b * 8);

        int s3 = it + NST;
        if (s3 < KTOT) {
            MBAR_WAIT(hdr + 24 + b * 8, (it / NST) & 1);
            do_load(s3, b);
            CPASYNC_ARRIVE_NOINC(hdr + b * 8);
        }
    }

#pragma unroll
    for (int mt = 0; mt < 2; mt++) {
#pragma unroll
        for (int nb = 0; nb < 4; nb++)
#pragma unroll
            for (int w = 0; w < 2; w++) {
                int nt = nb * 2 + w;
                int row0 = m0 + wm * 32 + mt * 16 + (lane >> 2);
                int col = n0 + wn * 64 + nb * 16 + w * 8 + (lane & 3) * 2;
                float2 v0 = make_float2(acc[mt][nt][0], acc[mt][nt][1]);
                float2 v1 = make_float2(acc[mt][nt][2], acc[mt][nt][3]);
                *reinterpret_cast<float2*>(out + (size_t)row0 * OUT_DIM + col) = v0;
                *reinterpret_cast<float2*>(out + (size_t)(row0 + 8) * OUT_DIM + col) = v1;
            }
    }
}

// ---------------------------------------------------------------------------
// Launch
// ---------------------------------------------------------------------------
extern "C" void kernel_launch(void* const* d_in, const int* in_sizes, int n_in,
                              void* d_out, int out_size) {
    const float* x      = (const float*)d_in[0];
    const int*   codes  = (const int*)d_in[1];
    const float* scales = (const float*)d_in[2];
    const float* lora_A = (const float*)d_in[3];
    const float* lora_B = (const float*)d_in[4];
    float* out = (float*)d_out;

    (void)in_sizes; (void)n_in; (void)out_size;

    // 1) streaming prep: x->fp16, dequant, B, A->fp16
    k_prep<<<PREP_GRID, 256>>>(x, lora_A, codes, scales, lora_B);

    // 2) Xa = 2*(Xh @ Ah^T) on tensor cores (8-way K-split, halved chain)
    cudaFuncSetAttribute(k_xa, cudaFuncAttributeMaxDynamicSharedMemorySize, XA_SMEM);
    k_xa<<<XA_CTAS, XA_THREADS, XA_SMEM>>>(0);

    // 3) GEMM: frozen best configuration (mbarrier pipeline, 65 K-slabs)
    cudaFuncSetAttribute(k_gemm, cudaFuncAttributeMaxDynamicSharedMemorySize, GEMM_SMEM);
    dim3 gg(OUT_DIM / BN, TOKENS / BM);
    k_gemm<<<gg, 256, GEMM_SMEM>>>(out);
}